// round 1
// baseline (speedup 1.0000x reference)
#include <cuda_runtime.h>
#include <cuda_bf16.h>

// Problem constants
#define BB 2
#define TT 2048
#define CC 1024
#define HH 16
#define HS 64
#define NROWS (BB*TT)   // 4096
#define M3C  (3*CC)     // 3072

// Scratch for Q/K/V in [B,H,T,HS] layout (16 MB each)
__device__ float g_q[BB*HH*TT*HS];
__device__ float g_k[BB*HH*TT*HS];
__device__ float g_v[BB*HH*TT*HS];

// ---------------------------------------------------------------------------
// Kernel 1: QKV projection.  qkv[n,m] = sum_c x[n,c]*W[m,c] + b[m]
// 128x128 tile, BK=8, 256 threads, 8x8 per thread (strided micro-tile).
// Epilogue scatters into g_q/g_k/g_v with [B,H,T,HS] layout; Q pre-scaled by 1/8.
// ---------------------------------------------------------------------------
__global__ __launch_bounds__(256) void qkv_gemm_kernel(
    const float* __restrict__ x,
    const float* __restrict__ W,
    const float* __restrict__ bias)
{
    __shared__ float As[8][129];
    __shared__ float Bs[8][129];

    const int tid = threadIdx.x;
    const int ty = tid >> 4;        // 0..15
    const int tx = tid & 15;        // 0..15
    const int n0 = blockIdx.x * 128;
    const int m0 = blockIdx.y * 128;

    const int arow = tid >> 1;           // 0..127
    const int ac4  = (tid & 1) * 4;      // 0 or 4
    const float* xrow = x + (size_t)(n0 + arow) * CC + ac4;
    const float* wrow = W + (size_t)(m0 + arow) * CC + ac4;

    float acc[8][8];
    #pragma unroll
    for (int i = 0; i < 8; i++)
        #pragma unroll
        for (int j = 0; j < 8; j++) acc[i][j] = 0.f;

    for (int k0 = 0; k0 < CC; k0 += 8) {
        float4 av = *(const float4*)(xrow + k0);
        float4 bv = *(const float4*)(wrow + k0);
        As[ac4 + 0][arow] = av.x;
        As[ac4 + 1][arow] = av.y;
        As[ac4 + 2][arow] = av.z;
        As[ac4 + 3][arow] = av.w;
        Bs[ac4 + 0][arow] = bv.x;
        Bs[ac4 + 1][arow] = bv.y;
        Bs[ac4 + 2][arow] = bv.z;
        Bs[ac4 + 3][arow] = bv.w;
        __syncthreads();

        #pragma unroll
        for (int kk = 0; kk < 8; kk++) {
            float a[8], b[8];
            #pragma unroll
            for (int i = 0; i < 8; i++) a[i] = As[kk][ty + 16 * i];
            #pragma unroll
            for (int j = 0; j < 8; j++) b[j] = Bs[kk][tx + 16 * j];
            #pragma unroll
            for (int i = 0; i < 8; i++)
                #pragma unroll
                for (int j = 0; j < 8; j++)
                    acc[i][j] = fmaf(a[i], b[j], acc[i][j]);
        }
        __syncthreads();
    }

    // Epilogue: add bias, scatter to Q/K/V scratch in [B,H,T,HS] layout.
    #pragma unroll
    for (int i = 0; i < 8; i++) {
        const int n = n0 + ty + 16 * i;
        const int b_ = n >> 11;        // n / 2048
        const int t  = n & 2047;
        #pragma unroll
        for (int j = 0; j < 8; j++) {
            const int m = m0 + tx + 16 * j;
            float v = acc[i][j] + bias[m];
            const int part = m >> 10;        // 0=q 1=k 2=v
            const int h = (m >> 6) & 15;
            const int d = m & 63;
            const int idx = (((b_ * HH + h) * TT + t) * HS) + d;
            if (part == 0)      g_q[idx] = v * 0.125f;   // fold scale = HS^-0.5
            else if (part == 1) g_k[idx] = v;
            else                g_v[idx] = v;
        }
    }
}

// ---------------------------------------------------------------------------
// Kernel 2: causal flash attention.
// grid = (T/64, B*H). One block: 64 q-rows of one (b,h).
// Q,K,V,S tiles in dynamic smem (stride 68 floats), O accumulator in regs.
// Warp-per-8-rows online softmax.
// ---------------------------------------------------------------------------
#define SMS 68                     // smem row stride (floats)
#define ATTN_SMEM (4 * 64 * SMS * 4)   // 69632 bytes

__global__ __launch_bounds__(256) void attn_kernel(float* __restrict__ out)
{
    extern __shared__ float sm[];
    float* Qs = sm;
    float* Ks = Qs + 64 * SMS;
    float* Vs = Ks + 64 * SMS;
    float* Ss = Vs + 64 * SMS;
    __shared__ float sm_m[64], sm_l[64], sm_a[64];

    const int tid = threadIdx.x;
    const int ty = tid >> 4, tx = tid & 15;
    const int lane = tid & 31, warp = tid >> 5;
    const int qt = blockIdx.x;        // q tile index (0..31)
    const int bh = blockIdx.y;        // b*H + h    (0..31)
    const int q0 = qt * 64;

    const float* Qg = g_q + (size_t)bh * (TT * HS);
    const float* Kg = g_k + (size_t)bh * (TT * HS);
    const float* Vg = g_v + (size_t)bh * (TT * HS);

    // Load Q tile (64x64) as float4s
    for (int idx = tid; idx < 64 * 16; idx += 256) {
        int r = idx >> 4, c4 = (idx & 15) * 4;
        *(float4*)(Qs + r * SMS + c4) = *(const float4*)(Qg + (q0 + r) * HS + c4);
    }
    if (tid < 64) { sm_m[tid] = -1e30f; sm_l[tid] = 0.f; }

    float acc[4][4];
    #pragma unroll
    for (int i = 0; i < 4; i++)
        #pragma unroll
        for (int j = 0; j < 4; j++) acc[i][j] = 0.f;

    for (int kt = 0; kt <= qt; kt++) {
        const int k0 = kt * 64;
        __syncthreads();   // previous iteration's readers of Ks/Vs done
        for (int idx = tid; idx < 64 * 16; idx += 256) {
            int r = idx >> 4, c4 = (idx & 15) * 4;
            *(float4*)(Ks + r * SMS + c4) = *(const float4*)(Kg + (k0 + r) * HS + c4);
            *(float4*)(Vs + r * SMS + c4) = *(const float4*)(Vg + (k0 + r) * HS + c4);
        }
        __syncthreads();

        // S = Q @ K^T  (Q already scaled)
        float s[4][4];
        #pragma unroll
        for (int i = 0; i < 4; i++)
            #pragma unroll
            for (int j = 0; j < 4; j++) s[i][j] = 0.f;

        #pragma unroll 8
        for (int kk = 0; kk < 64; kk++) {
            float a[4], b[4];
            #pragma unroll
            for (int i = 0; i < 4; i++) a[i] = Qs[(ty + 16 * i) * SMS + kk];
            #pragma unroll
            for (int j = 0; j < 4; j++) b[j] = Ks[(tx + 16 * j) * SMS + kk];
            #pragma unroll
            for (int i = 0; i < 4; i++)
                #pragma unroll
                for (int j = 0; j < 4; j++)
                    s[i][j] = fmaf(a[i], b[j], s[i][j]);
        }

        const bool diag = (kt == qt);
        #pragma unroll
        for (int i = 0; i < 4; i++) {
            #pragma unroll
            for (int j = 0; j < 4; j++) {
                if (diag && (k0 + tx + 16 * j) > (q0 + ty + 16 * i)) s[i][j] = -1e30f;
                Ss[(ty + 16 * i) * SMS + tx + 16 * j] = s[i][j];
            }
        }
        __syncthreads();

        // Online softmax: warp w handles rows [8w, 8w+8)
        for (int rr = 0; rr < 8; rr++) {
            const int row = warp * 8 + rr;
            float v0 = Ss[row * SMS + lane * 2];
            float v1 = Ss[row * SMS + lane * 2 + 1];
            float mx = fmaxf(v0, v1);
            #pragma unroll
            for (int off = 16; off; off >>= 1)
                mx = fmaxf(mx, __shfl_xor_sync(0xffffffffu, mx, off));
            const float m_old = sm_m[row];
            const float m_new = fmaxf(m_old, mx);
            const float p0 = __expf(v0 - m_new);
            const float p1 = __expf(v1 - m_new);
            Ss[row * SMS + lane * 2]     = p0;
            Ss[row * SMS + lane * 2 + 1] = p1;
            float ssum = p0 + p1;
            #pragma unroll
            for (int off = 16; off; off >>= 1)
                ssum += __shfl_xor_sync(0xffffffffu, ssum, off);
            if (lane == 0) {
                const float alpha = __expf(m_old - m_new);
                sm_l[row] = sm_l[row] * alpha + ssum;
                sm_m[row] = m_new;
                sm_a[row] = alpha;
            }
        }
        __syncthreads();

        // O = O*alpha + P @ V
        float ar[4];
        #pragma unroll
        for (int i = 0; i < 4; i++) ar[i] = sm_a[ty + 16 * i];
        #pragma unroll
        for (int i = 0; i < 4; i++)
            #pragma unroll
            for (int j = 0; j < 4; j++) acc[i][j] *= ar[i];

        #pragma unroll 8
        for (int kk = 0; kk < 64; kk++) {
            float p[4], v[4];
            #pragma unroll
            for (int i = 0; i < 4; i++) p[i] = Ss[(ty + 16 * i) * SMS + kk];
            #pragma unroll
            for (int j = 0; j < 4; j++) v[j] = Vs[kk * SMS + tx + 16 * j];
            #pragma unroll
            for (int i = 0; i < 4; i++)
                #pragma unroll
                for (int j = 0; j < 4; j++)
                    acc[i][j] = fmaf(p[i], v[j], acc[i][j]);
        }
    }

    // Final: divide by l, write out[b, t, h*64 + d]
    const int b_ = bh >> 4, h = bh & 15;
    #pragma unroll
    for (int i = 0; i < 4; i++) {
        const int row = ty + 16 * i;
        const float inv = 1.f / sm_l[row];
        const int t = q0 + row;
        #pragma unroll
        for (int j = 0; j < 4; j++) {
            out[((size_t)(b_ * TT + t)) * CC + h * HS + tx + 16 * j] = acc[i][j] * inv;
        }
    }
}

// ---------------------------------------------------------------------------
extern "C" void kernel_launch(void* const* d_in, const int* in_sizes, int n_in,
                              void* d_out, int out_size)
{
    const float* x    = (const float*)d_in[0];  // [B,T,C]
    const float* W    = (const float*)d_in[1];  // [3C,C]
    const float* bias = (const float*)d_in[2];  // [3C]
    float* out = (float*)d_out;                 // [B,T,C]

    cudaFuncSetAttribute(attn_kernel, cudaFuncAttributeMaxDynamicSharedMemorySize,
                         ATTN_SMEM);

    dim3 g1(NROWS / 128, M3C / 128);   // (32, 24)
    qkv_gemm_kernel<<<g1, 256>>>(x, W, bias);

    dim3 g2(TT / 64, BB * HH);         // (32, 32)
    attn_kernel<<<g2, 256, ATTN_SMEM>>>(out);
}

// round 4
// speedup vs baseline: 1.1511x; 1.1511x over previous
#include <cuda_runtime.h>
#include <cstdint>

// Problem constants
#define BB 2
#define TT 2048
#define CC 1024
#define HH 16
#define HS 64
#define NROWS (BB*TT)   // 4096
#define M3C  (3*CC)     // 3072

// Scratch for Q/K/V in [B,H,T,HS] layout (16 MB each)
__device__ float g_q[BB*HH*TT*HS];
__device__ float g_k[BB*HH*TT*HS];
__device__ float g_v[BB*HH*TT*HS];

// ===========================================================================
// Helpers (all plain-sm_100-legal PTX: mma.sync, cp.async, cvt.tf32)
// ===========================================================================
__device__ __forceinline__ uint32_t smem_u32(const void* p) {
    uint32_t a;
    asm("{ .reg .u64 t; cvta.to.shared.u64 t, %1; cvt.u32.u64 %0, t; }"
        : "=r"(a) : "l"(p));
    return a;
}

__device__ __forceinline__ void cp_async16(uint32_t dst, const void* src) {
    asm volatile("cp.async.cg.shared.global [%0], [%1], 16;"
                 :: "r"(dst), "l"(src));
}
#define CP_COMMIT() asm volatile("cp.async.commit_group;" ::: "memory")
#define CP_WAIT(n)  asm volatile("cp.async.wait_group %0;" :: "n"(n) : "memory")

// Split fp32 into tf32 hi + tf32 lo (error compensation)
__device__ __forceinline__ void split_tf32(float x, uint32_t& hi, uint32_t& lo) {
    asm("cvt.rna.tf32.f32 %0, %1;" : "=r"(hi) : "f"(x));
    float r = x - __uint_as_float(hi);
    asm("cvt.rna.tf32.f32 %0, %1;" : "=r"(lo) : "f"(r));
}

// D += A * B   (m16n8k8 tf32, fp32 accum)
__device__ __forceinline__ void mma_tf32(float d[4], const uint32_t a[4],
                                         const uint32_t b[2]) {
    asm volatile(
        "mma.sync.aligned.m16n8k8.row.col.f32.tf32.tf32.f32 "
        "{%0,%1,%2,%3}, {%4,%5,%6,%7}, {%8,%9}, {%0,%1,%2,%3};"
        : "+f"(d[0]), "+f"(d[1]), "+f"(d[2]), "+f"(d[3])
        : "r"(a[0]), "r"(a[1]), "r"(a[2]), "r"(a[3]),
          "r"(b[0]), "r"(b[1]));
}

// ===========================================================================
// Kernel 1: QKV projection via mma.sync tf32 (hi/lo compensated).
// C[4096,3072] = x @ W^T + b, scattered into g_q/g_k/g_v ([B,H,T,HS]).
// 128x128 CTA tile, 8 warps (2x4), warp tile 64x32, K-chunks of 32,
// double-buffered smem via cp.async. Stride 36 floats -> conflict-free LDS.
// ===========================================================================
#define GST 36                       // smem row stride (floats)
#define GBUF (128 * GST)             // 4608 floats per matrix buffer
#define GEMM_SMEM (2 * 2 * GBUF * 4) // 73728 bytes

__global__ __launch_bounds__(256) void qkv_gemm_mma(
    const float* __restrict__ x,
    const float* __restrict__ W,
    const float* __restrict__ bias)
{
    extern __shared__ float sm[];
    const int tid = threadIdx.x, lane = tid & 31, warp = tid >> 5;
    const int wm = warp & 1, wn = warp >> 1;   // warp grid 2 x 4
    const int g = lane >> 2, tg = lane & 3;    // fragment coords
    const int m0 = blockIdx.x * 128;           // token rows
    const int n0 = blockIdx.y * 128;           // output channels

    // cp.async coords: 4 float4 per matrix per chunk per thread
    int r_[4], c_[4];
    #pragma unroll
    for (int i = 0; i < 4; i++) {
        int idx = tid + 256 * i;
        r_[i] = idx >> 3;          // 0..127
        c_[i] = (idx & 7) * 4;     // 0,4,...,28
    }
    const uint32_t smbase = smem_u32(sm);

    float acc[4][4][4];
    #pragma unroll
    for (int mt = 0; mt < 4; mt++)
        #pragma unroll
        for (int nt = 0; nt < 4; nt++)
            #pragma unroll
            for (int q = 0; q < 4; q++) acc[mt][nt][q] = 0.f;

    // issue chunk ch into buffer ch&1
    #define GEMM_ISSUE(ch) do { \
        const int _b = (ch) & 1; \
        const uint32_t _ab = smbase + _b * (2 * GBUF) * 4; \
        const uint32_t _bb = _ab + GBUF * 4; \
        const float* _xs = x + (size_t)m0 * CC + (ch) * 32; \
        const float* _ws = W + (size_t)n0 * CC + (ch) * 32; \
        _Pragma("unroll") \
        for (int i = 0; i < 4; i++) { \
            cp_async16(_ab + (uint32_t)(r_[i] * GST + c_[i]) * 4, \
                       _xs + (size_t)r_[i] * CC + c_[i]); \
            cp_async16(_bb + (uint32_t)(r_[i] * GST + c_[i]) * 4, \
                       _ws + (size_t)r_[i] * CC + c_[i]); \
        } \
        CP_COMMIT(); \
    } while (0)

    GEMM_ISSUE(0);

    for (int ch = 0; ch < 32; ch++) {
        if (ch < 31) { GEMM_ISSUE(ch + 1); CP_WAIT(1); }
        else         { CP_WAIT(0); }
        __syncthreads();

        const float* As = sm + (ch & 1) * (2 * GBUF);
        const float* Bs = As + GBUF;

        #pragma unroll
        for (int ks = 0; ks < 4; ks++) {
            const int k0 = ks * 8;
            uint32_t ahi[4][4], alo[4][4], bhi[4][2], blo[4][2];
            #pragma unroll
            for (int mt = 0; mt < 4; mt++) {
                const int rb = wm * 64 + mt * 16 + g;
                float e0 = As[rb * GST + k0 + tg];
                float e1 = As[(rb + 8) * GST + k0 + tg];
                float e2 = As[rb * GST + k0 + tg + 4];
                float e3 = As[(rb + 8) * GST + k0 + tg + 4];
                split_tf32(e0, ahi[mt][0], alo[mt][0]);
                split_tf32(e1, ahi[mt][1], alo[mt][1]);
                split_tf32(e2, ahi[mt][2], alo[mt][2]);
                split_tf32(e3, ahi[mt][3], alo[mt][3]);
            }
            #pragma unroll
            for (int nt = 0; nt < 4; nt++) {
                const int cb = wn * 32 + nt * 8 + g;
                float f0 = Bs[cb * GST + k0 + tg];
                float f1 = Bs[cb * GST + k0 + tg + 4];
                split_tf32(f0, bhi[nt][0], blo[nt][0]);
                split_tf32(f1, bhi[nt][1], blo[nt][1]);
            }
            #pragma unroll
            for (int mt = 0; mt < 4; mt++)
                #pragma unroll
                for (int nt = 0; nt < 4; nt++) {
                    mma_tf32(acc[mt][nt], ahi[mt], bhi[nt]);
                    mma_tf32(acc[mt][nt], ahi[mt], blo[nt]);
                    mma_tf32(acc[mt][nt], alo[mt], bhi[nt]);
                }
        }
        __syncthreads();
    }

    // Epilogue: bias + scatter. Part (q/k/v) is uniform per CTA.
    const int part = blockIdx.y >> 3;
    float* dst = (part == 0) ? g_q : (part == 1) ? g_k : g_v;
    const float scl = (part == 0) ? 0.125f : 1.0f;   // fold 1/sqrt(HS) into Q

    #pragma unroll
    for (int nt = 0; nt < 4; nt++) {
        const int n = n0 + wn * 32 + nt * 8 + 2 * tg;  // even column
        const int h = (n >> 6) & 15;
        const int d = n & 63;
        const float bb0 = __ldg(bias + n);
        const float bb1 = __ldg(bias + n + 1);
        #pragma unroll
        for (int mt = 0; mt < 4; mt++) {
            const int m = m0 + wm * 64 + mt * 16 + g;
            {
                const int bi = m >> 11, t = m & 2047;
                const size_t i0 = (((size_t)(bi * HH + h)) * TT + t) * HS + d;
                float2 v;
                v.x = (acc[mt][nt][0] + bb0) * scl;
                v.y = (acc[mt][nt][1] + bb1) * scl;
                *(float2*)(dst + i0) = v;
            }
            {
                const int m2 = m + 8;
                const int bi = m2 >> 11, t = m2 & 2047;
                const size_t i1 = (((size_t)(bi * HH + h)) * TT + t) * HS + d;
                float2 v;
                v.x = (acc[mt][nt][2] + bb0) * scl;
                v.y = (acc[mt][nt][3] + bb1) * scl;
                *(float2*)(dst + i1) = v;
            }
        }
    }
}

// ===========================================================================
// Kernel 2: causal flash attention, vectorized-LDS SIMT microkernel.
// Block: 256 threads, 64 q-rows of one (b,h). Thread (ty,tx) owns rows
// 4ty..4ty+3 and cols 4tx..4tx+3. Q/K/P stored transposed over the reduction
// index with a 16-float4 XOR swizzle; softmax fully in registers via shfl.
// ===========================================================================
#define ATTN_SMEM ((12288 + 64 * 68) * 4 + 1024)

__global__ __launch_bounds__(256) void attn_simt(float* __restrict__ out)
{
    extern __shared__ char dsm2[];
    float* base = (float*)(((uintptr_t)dsm2 + 1023) & ~(uintptr_t)1023);
    float* Qt = base;            // [d][row], swizzled, 64x64
    float* Kt = base + 4096;     // [d][col], swizzled
    float* Pt = base + 8192;     // [key][row], swizzled
    float* Vs = base + 12288;    // [key][d], stride 68

    const int tid = threadIdx.x;
    const int ty = tid >> 4, tx = tid & 15;
    const int qt = blockIdx.x, bh = blockIdx.y;
    const int q0 = qt * 64;

    const float* Qg = g_q + (size_t)bh * (TT * HS);
    const float* Kg = g_k + (size_t)bh * (TT * HS);
    const float* Vg = g_v + (size_t)bh * (TT * HS);

    // Load Q transposed+swizzled: element (d, r) at Qt[d*64 + ((r>>2)^(d&15))*4 + (r&3)]
    #pragma unroll
    for (int i = 0; i < 4; i++) {
        int idx = tid + 256 * i;
        int t = idx & 63, d4 = (idx >> 6) << 2;
        float4 v = *(const float4*)(Qg + (size_t)(q0 + t) * HS + d4);
        int tq = t >> 2, tr = t & 3;
        Qt[(d4 + 0) * 64 + ((tq ^ ((d4 + 0) & 15)) << 2) + tr] = v.x;
        Qt[(d4 + 1) * 64 + ((tq ^ ((d4 + 1) & 15)) << 2) + tr] = v.y;
        Qt[(d4 + 2) * 64 + ((tq ^ ((d4 + 2) & 15)) << 2) + tr] = v.z;
        Qt[(d4 + 3) * 64 + ((tq ^ ((d4 + 3) & 15)) << 2) + tr] = v.w;
    }

    float m_[4], l_[4], acc[4][4];
    #pragma unroll
    for (int i = 0; i < 4; i++) {
        m_[i] = -1e30f; l_[i] = 0.f;
        #pragma unroll
        for (int j = 0; j < 4; j++) acc[i][j] = 0.f;
    }

    for (int kt = 0; kt <= qt; kt++) {
        const int k0 = kt * 64;
        __syncthreads();   // prev iteration readers of Kt/Vs/Pt done (also covers Qt init)

        #pragma unroll
        for (int i = 0; i < 4; i++) {
            int idx = tid + 256 * i;
            int t = idx & 63, d4 = (idx >> 6) << 2;
            int tq = t >> 2, tr = t & 3;
            float4 kv = *(const float4*)(Kg + (size_t)(k0 + t) * HS + d4);
            Kt[(d4 + 0) * 64 + ((tq ^ ((d4 + 0) & 15)) << 2) + tr] = kv.x;
            Kt[(d4 + 1) * 64 + ((tq ^ ((d4 + 1) & 15)) << 2) + tr] = kv.y;
            Kt[(d4 + 2) * 64 + ((tq ^ ((d4 + 2) & 15)) << 2) + tr] = kv.z;
            Kt[(d4 + 3) * 64 + ((tq ^ ((d4 + 3) & 15)) << 2) + tr] = kv.w;
            float4 vv = *(const float4*)(Vg + (size_t)(k0 + t) * HS + d4);
            *(float4*)(Vs + t * 68 + d4) = vv;
        }
        __syncthreads();

        // S = Q @ K^T (Q pre-scaled by 1/8 in the GEMM epilogue)
        float s[4][4];
        #pragma unroll
        for (int i = 0; i < 4; i++)
            #pragma unroll
            for (int j = 0; j < 4; j++) s[i][j] = 0.f;

        #pragma unroll 8
        for (int kk = 0; kk < 64; kk++) {
            const int sw = kk & 15;
            float4 a4 = *(const float4*)(Qt + kk * 64 + ((ty ^ sw) << 2));
            float4 b4 = *(const float4*)(Kt + kk * 64 + ((tx ^ sw) << 2));
            float av[4] = {a4.x, a4.y, a4.z, a4.w};
            float bv[4] = {b4.x, b4.y, b4.z, b4.w};
            #pragma unroll
            for (int i = 0; i < 4; i++)
                #pragma unroll
                for (int j = 0; j < 4; j++)
                    s[i][j] = fmaf(av[i], bv[j], s[i][j]);
        }

        if (kt == qt) {   // diagonal tile: causal mask
            #pragma unroll
            for (int i = 0; i < 4; i++)
                #pragma unroll
                for (int j = 0; j < 4; j++)
                    if (4 * tx + j > 4 * ty + i) s[i][j] = -1e30f;
        }

        // Register softmax: reduce across the 16-lane tx group via shfl_xor
        float al[4];
        #pragma unroll
        for (int i = 0; i < 4; i++) {
            float mi = fmaxf(fmaxf(s[i][0], s[i][1]), fmaxf(s[i][2], s[i][3]));
            #pragma unroll
            for (int off = 1; off < 16; off <<= 1)
                mi = fmaxf(mi, __shfl_xor_sync(0xffffffffu, mi, off));
            const float mn = fmaxf(m_[i], mi);
            float su = 0.f;
            #pragma unroll
            for (int j = 0; j < 4; j++) {
                s[i][j] = __expf(s[i][j] - mn);
                su += s[i][j];
            }
            #pragma unroll
            for (int off = 1; off < 16; off <<= 1)
                su += __shfl_xor_sync(0xffffffffu, su, off);
            al[i] = __expf(m_[i] - mn);
            l_[i] = l_[i] * al[i] + su;
            m_[i] = mn;
        }
        #pragma unroll
        for (int i = 0; i < 4; i++)
            #pragma unroll
            for (int j = 0; j < 4; j++) acc[i][j] *= al[i];

        // Write P transposed: element (c=key, r=row), float4 over rows
        #pragma unroll
        for (int j = 0; j < 4; j++) {
            const int c = 4 * tx + j;
            float4 pv;
            pv.x = s[0][j]; pv.y = s[1][j]; pv.z = s[2][j]; pv.w = s[3][j];
            *(float4*)(Pt + c * 64 + ((ty ^ (c & 15)) << 2)) = pv;
        }
        __syncthreads();

        // O += P @ V
        #pragma unroll 8
        for (int kk = 0; kk < 64; kk++) {
            float4 p4 = *(const float4*)(Pt + kk * 64 + ((ty ^ (kk & 15)) << 2));
            float4 v4 = *(const float4*)(Vs + kk * 68 + 4 * tx);
            float pv[4] = {p4.x, p4.y, p4.z, p4.w};
            float vv[4] = {v4.x, v4.y, v4.z, v4.w};
            #pragma unroll
            for (int i = 0; i < 4; i++)
                #pragma unroll
                for (int j = 0; j < 4; j++)
                    acc[i][j] = fmaf(pv[i], vv[j], acc[i][j]);
        }
    }

    // Epilogue: divide by l, write out[b, t, h*64 + d] (float4, coalesced)
    const int b_ = bh >> 4, h = bh & 15;
    #pragma unroll
    for (int i = 0; i < 4; i++) {
        const int t = q0 + 4 * ty + i;
        const float inv = 1.f / l_[i];
        float4 o;
        o.x = acc[i][0] * inv;
        o.y = acc[i][1] * inv;
        o.z = acc[i][2] * inv;
        o.w = acc[i][3] * inv;
        *(float4*)(out + ((size_t)(b_ * TT + t)) * CC + h * HS + 4 * tx) = o;
    }
}

// ===========================================================================
extern "C" void kernel_launch(void* const* d_in, const int* in_sizes, int n_in,
                              void* d_out, int out_size)
{
    const float* x    = (const float*)d_in[0];  // [B,T,C]
    const float* W    = (const float*)d_in[1];  // [3C,C]
    const float* bias = (const float*)d_in[2];  // [3C]
    float* out = (float*)d_out;                 // [B,T,C]

    cudaFuncSetAttribute(qkv_gemm_mma, cudaFuncAttributeMaxDynamicSharedMemorySize,
                         GEMM_SMEM);
    cudaFuncSetAttribute(attn_simt, cudaFuncAttributeMaxDynamicSharedMemorySize,
                         ATTN_SMEM);

    dim3 g1(NROWS / 128, M3C / 128);   // (32, 24)
    qkv_gemm_mma<<<g1, 256, GEMM_SMEM>>>(x, W, bias);

    dim3 g2(TT / 64, BB * HH);         // (32, 32)
    attn_simt<<<g2, 256, ATTN_SMEM>>>(out);
}

// round 5
// speedup vs baseline: 1.7900x; 1.5551x over previous
#include <cuda_runtime.h>
#include <cstdint>

// Problem constants
#define BB 2
#define TT 2048
#define CC 1024
#define HH 16
#define HS 64
#define NROWS (BB*TT)   // 4096
#define M3C  (3*CC)     // 3072

// Scratch for Q/K/V in [B,H,T,HS] layout (16 MB each)
__device__ float g_q[BB*HH*TT*HS];
__device__ float g_k[BB*HH*TT*HS];
__device__ float g_v[BB*HH*TT*HS];

// ===========================================================================
// Helpers (plain-sm_100-legal PTX: mma.sync, cp.async, cvt.tf32)
// ===========================================================================
__device__ __forceinline__ uint32_t smem_u32(const void* p) {
    uint32_t a;
    asm("{ .reg .u64 t; cvta.to.shared.u64 t, %1; cvt.u32.u64 %0, t; }"
        : "=r"(a) : "l"(p));
    return a;
}

__device__ __forceinline__ void cp_async16(uint32_t dst, const void* src) {
    asm volatile("cp.async.cg.shared.global [%0], [%1], 16;"
                 :: "r"(dst), "l"(src));
}
#define CP_COMMIT() asm volatile("cp.async.commit_group;" ::: "memory")
#define CP_WAIT(n)  asm volatile("cp.async.wait_group %0;" :: "n"(n) : "memory")

// Split fp32 into tf32 hi + tf32 lo (error compensation)
__device__ __forceinline__ void split_tf32(float x, uint32_t& hi, uint32_t& lo) {
    asm("cvt.rna.tf32.f32 %0, %1;" : "=r"(hi) : "f"(x));
    float r = x - __uint_as_float(hi);
    asm("cvt.rna.tf32.f32 %0, %1;" : "=r"(lo) : "f"(r));
}
__device__ __forceinline__ void split_tf32_f(float x, float& hi, float& lo) {
    uint32_t h, l;
    split_tf32(x, h, l);
    hi = __uint_as_float(h);
    lo = __uint_as_float(l);
}

// D += A * B   (m16n8k8 tf32, fp32 accum)
__device__ __forceinline__ void mma_tf32(float d[4], const uint32_t a[4],
                                         const uint32_t b[2]) {
    asm volatile(
        "mma.sync.aligned.m16n8k8.row.col.f32.tf32.tf32.f32 "
        "{%0,%1,%2,%3}, {%4,%5,%6,%7}, {%8,%9}, {%0,%1,%2,%3};"
        : "+f"(d[0]), "+f"(d[1]), "+f"(d[2]), "+f"(d[3])
        : "r"(a[0]), "r"(a[1]), "r"(a[2]), "r"(a[3]),
          "r"(b[0]), "r"(b[1]));
}

// ===========================================================================
// Kernel 1: QKV projection via mma.sync tf32 (hi/lo compensated).
// (unchanged from Round 4 — passed at ~457us)
// ===========================================================================
#define GST 36                       // smem row stride (floats)
#define GBUF (128 * GST)             // 4608 floats per matrix buffer
#define GEMM_SMEM (2 * 2 * GBUF * 4) // 73728 bytes

__global__ __launch_bounds__(256) void qkv_gemm_mma(
    const float* __restrict__ x,
    const float* __restrict__ W,
    const float* __restrict__ bias)
{
    extern __shared__ float sm[];
    const int tid = threadIdx.x, lane = tid & 31, warp = tid >> 5;
    const int wm = warp & 1, wn = warp >> 1;   // warp grid 2 x 4
    const int g = lane >> 2, tg = lane & 3;    // fragment coords
    const int m0 = blockIdx.x * 128;           // token rows
    const int n0 = blockIdx.y * 128;           // output channels

    int r_[4], c_[4];
    #pragma unroll
    for (int i = 0; i < 4; i++) {
        int idx = tid + 256 * i;
        r_[i] = idx >> 3;
        c_[i] = (idx & 7) * 4;
    }
    const uint32_t smbase = smem_u32(sm);

    float acc[4][4][4];
    #pragma unroll
    for (int mt = 0; mt < 4; mt++)
        #pragma unroll
        for (int nt = 0; nt < 4; nt++)
            #pragma unroll
            for (int q = 0; q < 4; q++) acc[mt][nt][q] = 0.f;

    #define GEMM_ISSUE(ch) do { \
        const int _b = (ch) & 1; \
        const uint32_t _ab = smbase + _b * (2 * GBUF) * 4; \
        const uint32_t _bb = _ab + GBUF * 4; \
        const float* _xs = x + (size_t)m0 * CC + (ch) * 32; \
        const float* _ws = W + (size_t)n0 * CC + (ch) * 32; \
        _Pragma("unroll") \
        for (int i = 0; i < 4; i++) { \
            cp_async16(_ab + (uint32_t)(r_[i] * GST + c_[i]) * 4, \
                       _xs + (size_t)r_[i] * CC + c_[i]); \
            cp_async16(_bb + (uint32_t)(r_[i] * GST + c_[i]) * 4, \
                       _ws + (size_t)r_[i] * CC + c_[i]); \
        } \
        CP_COMMIT(); \
    } while (0)

    GEMM_ISSUE(0);

    for (int ch = 0; ch < 32; ch++) {
        if (ch < 31) { GEMM_ISSUE(ch + 1); CP_WAIT(1); }
        else         { CP_WAIT(0); }
        __syncthreads();

        const float* As = sm + (ch & 1) * (2 * GBUF);
        const float* Bs = As + GBUF;

        #pragma unroll
        for (int ks = 0; ks < 4; ks++) {
            const int k0 = ks * 8;
            uint32_t ahi[4][4], alo[4][4], bhi[4][2], blo[4][2];
            #pragma unroll
            for (int mt = 0; mt < 4; mt++) {
                const int rb = wm * 64 + mt * 16 + g;
                float e0 = As[rb * GST + k0 + tg];
                float e1 = As[(rb + 8) * GST + k0 + tg];
                float e2 = As[rb * GST + k0 + tg + 4];
                float e3 = As[(rb + 8) * GST + k0 + tg + 4];
                split_tf32(e0, ahi[mt][0], alo[mt][0]);
                split_tf32(e1, ahi[mt][1], alo[mt][1]);
                split_tf32(e2, ahi[mt][2], alo[mt][2]);
                split_tf32(e3, ahi[mt][3], alo[mt][3]);
            }
            #pragma unroll
            for (int nt = 0; nt < 4; nt++) {
                const int cb = wn * 32 + nt * 8 + g;
                float f0 = Bs[cb * GST + k0 + tg];
                float f1 = Bs[cb * GST + k0 + tg + 4];
                split_tf32(f0, bhi[nt][0], blo[nt][0]);
                split_tf32(f1, bhi[nt][1], blo[nt][1]);
            }
            #pragma unroll
            for (int mt = 0; mt < 4; mt++)
                #pragma unroll
                for (int nt = 0; nt < 4; nt++) {
                    mma_tf32(acc[mt][nt], ahi[mt], bhi[nt]);
                    mma_tf32(acc[mt][nt], ahi[mt], blo[nt]);
                    mma_tf32(acc[mt][nt], alo[mt], bhi[nt]);
                }
        }
        __syncthreads();
    }

    const int part = blockIdx.y >> 3;
    float* dst = (part == 0) ? g_q : (part == 1) ? g_k : g_v;
    const float scl = (part == 0) ? 0.125f : 1.0f;

    #pragma unroll
    for (int nt = 0; nt < 4; nt++) {
        const int n = n0 + wn * 32 + nt * 8 + 2 * tg;
        const int h = (n >> 6) & 15;
        const int d = n & 63;
        const float bb0 = __ldg(bias + n);
        const float bb1 = __ldg(bias + n + 1);
        #pragma unroll
        for (int mt = 0; mt < 4; mt++) {
            const int m = m0 + wm * 64 + mt * 16 + g;
            {
                const int bi = m >> 11, t = m & 2047;
                const size_t i0 = (((size_t)(bi * HH + h)) * TT + t) * HS + d;
                float2 v;
                v.x = (acc[mt][nt][0] + bb0) * scl;
                v.y = (acc[mt][nt][1] + bb1) * scl;
                *(float2*)(dst + i0) = v;
            }
            {
                const int m2 = m + 8;
                const int bi = m2 >> 11, t = m2 & 2047;
                const size_t i1 = (((size_t)(bi * HH + h)) * TT + t) * HS + d;
                float2 v;
                v.x = (acc[mt][nt][2] + bb0) * scl;
                v.y = (acc[mt][nt][3] + bb1) * scl;
                *(float2*)(dst + i1) = v;
            }
        }
    }
}

// ===========================================================================
// Kernel 2: causal flash attention on mma.sync tf32 (hi/lo compensated).
// CTA = 128 q-rows of one (b,h); 8 warps, each an m16 row slab.
// Key tiles of 64. K/V pre-split into hi/lo smem tiles (shared by all
// warps); Q fragments persistent in registers; softmax in C-fragments via
// quad shfl; P routed through warp-private smem slab (syncwarp only).
// Strides: K 68, V 72, P 68 -> all fragment LDS conflict-free.
// ===========================================================================
#define KST 68
#define VST 72
#define PST 68
#define ATTN_SMEM ((64*KST*2 + 64*VST*2 + 128*PST) * 4)   // 106496 B

__global__ __launch_bounds__(256) void attn_mma(float* __restrict__ out)
{
    extern __shared__ float asmem[];
    float* Khi = asmem;
    float* Klo = Khi + 64 * KST;
    float* Vhi = Klo + 64 * KST;
    float* Vlo = Vhi + 64 * VST;
    float* Ps  = Vlo + 64 * VST;

    const int tid = threadIdx.x, lane = tid & 31, wid = tid >> 5;
    const int g = lane >> 2, tg = lane & 3;
    const int qt = 15 - blockIdx.x;          // heavy CTAs first
    const int bh = blockIdx.y;
    const int q0 = qt * 128;
    const int wq = wid * 16;                 // warp's row slab within CTA

    const float* Qg = g_q + (size_t)bh * (TT * HS);
    const float* Kg = g_k + (size_t)bh * (TT * HS);
    const float* Vg = g_v + (size_t)bh * (TT * HS);

    // --- Persistent Q fragments (already scaled by 1/8 in GEMM epilogue) ---
    uint32_t qhi[8][4], qlo[8][4];
    {
        const float* qr0 = Qg + (size_t)(q0 + wq + g) * HS;
        const float* qr1 = qr0 + 8 * HS;
        #pragma unroll
        for (int ks = 0; ks < 8; ks++) {
            split_tf32(qr0[8 * ks + tg],     qhi[ks][0], qlo[ks][0]);
            split_tf32(qr1[8 * ks + tg],     qhi[ks][1], qlo[ks][1]);
            split_tf32(qr0[8 * ks + tg + 4], qhi[ks][2], qlo[ks][2]);
            split_tf32(qr1[8 * ks + tg + 4], qhi[ks][3], qlo[ks][3]);
        }
    }

    // Online-softmax state for the two rows this thread co-owns (g, g+8)
    float m0r = -1e30f, m1r = -1e30f, l0r = 0.f, l1r = 0.f;
    float o[8][4];
    #pragma unroll
    for (int nt = 0; nt < 8; nt++)
        #pragma unroll
        for (int q = 0; q < 4; q++) o[nt][q] = 0.f;

    const int nkt = 2 * qt + 2;              // key tiles (causal)
    for (int kt = 0; kt < nkt; kt++) {
        const int k0 = kt * 64;
        __syncthreads();   // all warps done reading prev K/V tiles

        // Cooperative load + hi/lo split of K and V (64x64 each)
        #pragma unroll
        for (int i = 0; i < 4; i++) {
            const int lin = tid + 256 * i;
            const int row = lin >> 4;            // 0..63
            const int c4 = (lin & 15) * 4;
            float4 kv = *(const float4*)(Kg + (size_t)(k0 + row) * HS + c4);
            float4 h, l;
            split_tf32_f(kv.x, h.x, l.x);
            split_tf32_f(kv.y, h.y, l.y);
            split_tf32_f(kv.z, h.z, l.z);
            split_tf32_f(kv.w, h.w, l.w);
            *(float4*)(Khi + row * KST + c4) = h;
            *(float4*)(Klo + row * KST + c4) = l;
            float4 vv = *(const float4*)(Vg + (size_t)(k0 + row) * HS + c4);
            split_tf32_f(vv.x, h.x, l.x);
            split_tf32_f(vv.y, h.y, l.y);
            split_tf32_f(vv.z, h.z, l.z);
            split_tf32_f(vv.w, h.w, l.w);
            *(float4*)(Vhi + row * VST + c4) = h;
            *(float4*)(Vlo + row * VST + c4) = l;
        }
        __syncthreads();

        // ---- S = Q @ K^T (c-fragments) ----
        float sc[8][4];
        #pragma unroll
        for (int nt = 0; nt < 8; nt++)
            #pragma unroll
            for (int q = 0; q < 4; q++) sc[nt][q] = 0.f;

        #pragma unroll
        for (int nt = 0; nt < 8; nt++) {
            const int krow = (nt * 8 + g) * KST;
            #pragma unroll
            for (int ks = 0; ks < 8; ks++) {
                uint32_t bh_[2], bl_[2];
                bh_[0] = __float_as_uint(Khi[krow + 8 * ks + tg]);
                bh_[1] = __float_as_uint(Khi[krow + 8 * ks + tg + 4]);
                bl_[0] = __float_as_uint(Klo[krow + 8 * ks + tg]);
                bl_[1] = __float_as_uint(Klo[krow + 8 * ks + tg + 4]);
                mma_tf32(sc[nt], qhi[ks], bh_);
                mma_tf32(sc[nt], qhi[ks], bl_);
                mma_tf32(sc[nt], qlo[ks], bh_);
            }
        }

        // ---- causal mask (only tiles overlapping the diagonal) ----
        const int r0 = q0 + wq + g;
        const int r1 = r0 + 8;
        if (k0 + 63 > r0) {
            #pragma unroll
            for (int nt = 0; nt < 8; nt++) {
                const int c = k0 + nt * 8 + 2 * tg;
                if (c > r0)     sc[nt][0] = -1e30f;
                if (c + 1 > r0) sc[nt][1] = -1e30f;
                if (c > r1)     sc[nt][2] = -1e30f;
                if (c + 1 > r1) sc[nt][3] = -1e30f;
            }
        }

        // ---- online softmax in registers (quad shfl over row owners) ----
        float mx0 = -1e30f, mx1 = -1e30f;
        #pragma unroll
        for (int nt = 0; nt < 8; nt++) {
            mx0 = fmaxf(mx0, fmaxf(sc[nt][0], sc[nt][1]));
            mx1 = fmaxf(mx1, fmaxf(sc[nt][2], sc[nt][3]));
        }
        mx0 = fmaxf(mx0, __shfl_xor_sync(0xffffffffu, mx0, 1));
        mx0 = fmaxf(mx0, __shfl_xor_sync(0xffffffffu, mx0, 2));
        mx1 = fmaxf(mx1, __shfl_xor_sync(0xffffffffu, mx1, 1));
        mx1 = fmaxf(mx1, __shfl_xor_sync(0xffffffffu, mx1, 2));
        const float mn0 = fmaxf(m0r, mx0);
        const float mn1 = fmaxf(m1r, mx1);

        float su0 = 0.f, su1 = 0.f;
        #pragma unroll
        for (int nt = 0; nt < 8; nt++) {
            sc[nt][0] = __expf(sc[nt][0] - mn0);
            sc[nt][1] = __expf(sc[nt][1] - mn0);
            sc[nt][2] = __expf(sc[nt][2] - mn1);
            sc[nt][3] = __expf(sc[nt][3] - mn1);
            su0 += sc[nt][0] + sc[nt][1];
            su1 += sc[nt][2] + sc[nt][3];
        }
        su0 += __shfl_xor_sync(0xffffffffu, su0, 1);
        su0 += __shfl_xor_sync(0xffffffffu, su0, 2);
        su1 += __shfl_xor_sync(0xffffffffu, su1, 1);
        su1 += __shfl_xor_sync(0xffffffffu, su1, 2);

        const float al0 = __expf(m0r - mn0);
        const float al1 = __expf(m1r - mn1);
        l0r = l0r * al0 + su0;
        l1r = l1r * al1 + su1;
        m0r = mn0;
        m1r = mn1;

        #pragma unroll
        for (int nt = 0; nt < 8; nt++) {
            o[nt][0] *= al0;
            o[nt][1] *= al0;
            o[nt][2] *= al1;
            o[nt][3] *= al1;
        }

        // ---- write P (C-frag -> warp-private smem slab) ----
        float* pr0 = Ps + (wq + g) * PST;
        float* pr1 = Ps + (wq + g + 8) * PST;
        #pragma unroll
        for (int nt = 0; nt < 8; nt++) {
            *(float2*)(pr0 + 8 * nt + 2 * tg) = make_float2(sc[nt][0], sc[nt][1]);
            *(float2*)(pr1 + 8 * nt + 2 * tg) = make_float2(sc[nt][2], sc[nt][3]);
        }
        __syncwarp();

        // ---- O += P @ V ----
        #pragma unroll
        for (int ks = 0; ks < 8; ks++) {
            uint32_t phi[4], plo[4];
            split_tf32(pr0[8 * ks + tg],     phi[0], plo[0]);
            split_tf32(pr1[8 * ks + tg],     phi[1], plo[1]);
            split_tf32(pr0[8 * ks + tg + 4], phi[2], plo[2]);
            split_tf32(pr1[8 * ks + tg + 4], phi[3], plo[3]);
            const int vr0 = (8 * ks + tg) * VST;
            const int vr1 = (8 * ks + tg + 4) * VST;
            #pragma unroll
            for (int nt = 0; nt < 8; nt++) {
                uint32_t bh_[2], bl_[2];
                bh_[0] = __float_as_uint(Vhi[vr0 + 8 * nt + g]);
                bh_[1] = __float_as_uint(Vhi[vr1 + 8 * nt + g]);
                bl_[0] = __float_as_uint(Vlo[vr0 + 8 * nt + g]);
                bl_[1] = __float_as_uint(Vlo[vr1 + 8 * nt + g]);
                mma_tf32(o[nt], phi, bh_);
                mma_tf32(o[nt], phi, bl_);
                mma_tf32(o[nt], plo, bh_);
            }
        }
        __syncwarp();   // P slab reads done before next iteration overwrites
    }

    // ---- epilogue: divide by l, write out[b, t, h*64 + d] ----
    const int b_ = bh >> 4, h = bh & 15;
    const float inv0 = 1.f / l0r;
    const float inv1 = 1.f / l1r;
    const int t0 = q0 + wq + g;
    const int t1 = t0 + 8;
    float* o0 = out + ((size_t)(b_ * TT + t0)) * CC + h * HS;
    float* o1 = out + ((size_t)(b_ * TT + t1)) * CC + h * HS;
    #pragma unroll
    for (int nt = 0; nt < 8; nt++) {
        *(float2*)(o0 + 8 * nt + 2 * tg) = make_float2(o[nt][0] * inv0, o[nt][1] * inv0);
        *(float2*)(o1 + 8 * nt + 2 * tg) = make_float2(o[nt][2] * inv1, o[nt][3] * inv1);
    }
}

// ===========================================================================
extern "C" void kernel_launch(void* const* d_in, const int* in_sizes, int n_in,
                              void* d_out, int out_size)
{
    const float* x    = (const float*)d_in[0];  // [B,T,C]
    const float* W    = (const float*)d_in[1];  // [3C,C]
    const float* bias = (const float*)d_in[2];  // [3C]
    float* out = (float*)d_out;                 // [B,T,C]

    cudaFuncSetAttribute(qkv_gemm_mma, cudaFuncAttributeMaxDynamicSharedMemorySize,
                         GEMM_SMEM);
    cudaFuncSetAttribute(attn_mma, cudaFuncAttributeMaxDynamicSharedMemorySize,
                         ATTN_SMEM);

    dim3 g1(NROWS / 128, M3C / 128);   // (32, 24)
    qkv_gemm_mma<<<g1, 256, GEMM_SMEM>>>(x, W, bias);

    dim3 g2(TT / 128, BB * HH);        // (16, 32)
    attn_mma<<<g2, 256, ATTN_SMEM>>>(out);
}